// round 3
// baseline (speedup 1.0000x reference)
#include <cuda_runtime.h>
#include <cuda_bf16.h>

// Problem constants
#define OUT_NUM 1024
#define LUT_NUM 64
#define LUT_K   6
#define BR      32                 // 16 batch * 2
#define FEAT    (LUT_NUM * LUT_K)  // 384

// y(b,r,out,lut) = 6-level binary-tree lerp over wq = sigmoid(2w).
//
// R3 layout: each (out,lut) tree is split across a THREAD QUAD on leaf bits
// (4,5). Thread q of the quad owns leaves [16q, 16q+16): base[8]+d[8] in
// registers, evaluates the 4-level subtree (bits 0..3), then two shfl_xor
// levels (mask 1 -> bit4, mask 2 -> bit5) combine the quad. Quadruples the
// warp pool vs R1 (2048 -> 8192 warps) — R1/R2 ncu both showed pure
// occupancy/issue limiting (R2: occ 37.9%, issue 43.8%, DRAM 39%, FMA 25%).
// Quad-duplicated x loads dedup in the coalescer, so L1 sector traffic stays
// flat.

__global__ __launch_bounds__(256, 6)
void lut_tree_kernel(const float* __restrict__ x,
                     const float* __restrict__ w,
                     float* __restrict__ out)
{
    const int tid  = threadIdx.x;       // 0..255
    const int lut  = tid >> 2;          // 0..63
    const int quad = tid & 3;           // (bit4, bit5) = (quad&1, quad>>1)
    const int o    = blockIdx.x;        // 0..1023

    // ---- my 16 contiguous w floats (64B per thread, warp fully coalesced) ----
    const float4* wp = reinterpret_cast<const float4*>(
        w + (((size_t)o * LUT_NUM + lut) << 6) + (quad << 4));

    float base[8], d[8];
#pragma unroll
    for (int i = 0; i < 4; ++i) {
        float4 v = wp[i];
        // sigmoid(2w) == (tanh(w)+1)/2 ; abs err ~1e-6 << 1e-3 gate
        float s0 = __fdividef(1.0f, 1.0f + __expf(-2.0f * v.x));
        float s1 = __fdividef(1.0f, 1.0f + __expf(-2.0f * v.y));
        float s2 = __fdividef(1.0f, 1.0f + __expf(-2.0f * v.z));
        float s3 = __fdividef(1.0f, 1.0f + __expf(-2.0f * v.w));
        base[2 * i]     = s0;  d[2 * i]     = s1 - s0;
        base[2 * i + 1] = s2;  d[2 * i + 1] = s3 - s2;
    }

    // ---- per-(b,r) tree evaluation ----
    const float* xp = x + (size_t)o * FEAT + lut * LUT_K;   // 8B aligned
    float*       op = out + (size_t)o * LUT_NUM + lut;

    for (int br = 0; br < BR; ++br) {          // NOT unrolled: L0 I$-resident body
        const float* xb = xp + (size_t)br * ((size_t)OUT_NUM * FEAT);
        float2 b01 = *reinterpret_cast<const float2*>(xb);       // bits 0,1
        float2 b23 = *reinterpret_cast<const float2*>(xb + 2);   // bits 2,3
        float2 b45 = *reinterpret_cast<const float2*>(xb + 4);   // bits 4,5

        float y[8];
        // level 0 (bit0)
#pragma unroll
        for (int i = 0; i < 8; ++i) y[i] = fmaf(b01.x, d[i], base[i]);
        // levels 1..3
#pragma unroll
        for (int i = 0; i < 4; ++i) y[i] = fmaf(b01.y, y[2 * i + 1] - y[2 * i], y[2 * i]);
#pragma unroll
        for (int i = 0; i < 2; ++i) y[i] = fmaf(b23.x, y[2 * i + 1] - y[2 * i], y[2 * i]);
        float v = fmaf(b23.y, y[1] - y[0], y[0]);   // subtree value (bits 0..3 applied)

        // level 4 (bit4): combine across quad&1
        float v1 = __shfl_xor_sync(0xFFFFFFFFu, v, 1);
        float lo4 = (quad & 1) ? v1 : v;
        float hi4 = (quad & 1) ? v : v1;
        v = fmaf(b45.x, hi4 - lo4, lo4);

        // level 5 (bit5): combine across quad>>1
        float v2 = __shfl_xor_sync(0xFFFFFFFFu, v, 2);
        float lo5 = (quad >> 1) ? v2 : v;
        float hi5 = (quad >> 1) ? v : v2;
        float r = fmaf(b45.y, hi5 - lo5, lo5);

        if (quad == 0)
            op[(size_t)br * ((size_t)OUT_NUM * LUT_NUM)] = r;
    }
}

extern "C" void kernel_launch(void* const* d_in, const int* in_sizes, int n_in,
                              void* d_out, int out_size)
{
    const float* x = (const float*)d_in[0];
    const float* w = (const float*)d_in[1];
    if (n_in >= 2 && in_sizes[0] < in_sizes[1]) {   // hedge on input order
        const float* t = x; x = w; w = t;
    }
    float* out = (float*)d_out;

    lut_tree_kernel<<<OUT_NUM, 256>>>(x, w, out);
}